// round 1
// baseline (speedup 1.0000x reference)
#include <cuda_runtime.h>
#include <cstdint>

#define Nn 50000
#define Ee 500000
#define ETOT (Nn + Ee)
#define FULL 0xffffffffu

// ---------------- scratch (static __device__, no allocation) ----------------
__device__ int   g_rowptr[Nn + 1];
__device__ int   g_cursor[Nn];
__device__ int   g_colsrc[ETOT];
__device__ float g_h[Nn * 128];       // post-GEMM features for current layer
__device__ float g_out0[Nn * 128];    // layer-0 output
__device__ float g_out1[Nn * 128];    // layer-1 output
__device__ float g_resid[Nn * 128];   // h0 @ R1W
__device__ float g_as[Nn * 4];
__device__ float g_ad[Nn * 4];
__device__ float g_h2p[Nn * 40];      // h1 @ W2
__device__ float g_resid2[Nn * 40];   // h1 @ R2W + R2b
__device__ float g_h2[Nn * 40];       // layer-2 output
__device__ float g_as2[Nn];
__device__ float g_ad2[Nn];

// ---------------- helpers ----------------
__device__ __forceinline__ float lrelu(float x) { return x > 0.f ? x : 0.2f * x; }

__device__ __forceinline__ float wred_max(float v) {
#pragma unroll
    for (int o = 16; o; o >>= 1) v = fmaxf(v, __shfl_xor_sync(FULL, v, o));
    return v;
}
__device__ __forceinline__ float wred_sum(float v) {
#pragma unroll
    for (int o = 16; o; o >>= 1) v += __shfl_xor_sync(FULL, v, o);
    return v;
}

// ---------------- CSR build ----------------
__global__ void k_init() {
    int i = blockIdx.x * blockDim.x + threadIdx.x;
    if (i < Nn) g_cursor[i] = 1;   // self loop
}

__global__ void k_hist(const int* __restrict__ dst) {
    int e = blockIdx.x * blockDim.x + threadIdx.x;
    if (e < Ee) atomicAdd(&g_cursor[dst[e]], 1);
}

// one-block exclusive scan of g_cursor -> g_rowptr; also place self loops and init cursors
__global__ void __launch_bounds__(1024) k_scan() {
    __shared__ int sums[1024];
    int t = threadIdx.x;
    const int CH = (Nn + 1023) / 1024;
    int base = t * CH;
    int local = 0;
    for (int i = 0; i < CH; i++) {
        int idx = base + i;
        if (idx < Nn) local += g_cursor[idx];
    }
    sums[t] = local;
    __syncthreads();
    for (int off = 1; off < 1024; off <<= 1) {
        int v = (t >= off) ? sums[t - off] : 0;
        __syncthreads();
        sums[t] += v;
        __syncthreads();
    }
    int prefix = (t == 0) ? 0 : sums[t - 1];
    for (int i = 0; i < CH; i++) {
        int idx = base + i;
        if (idx < Nn) {
            int d = g_cursor[idx];
            g_rowptr[idx] = prefix;
            g_colsrc[prefix] = idx;       // self loop at slot 0 of segment
            g_cursor[idx] = prefix + 1;   // cursor for scatter
            prefix += d;
        }
    }
    if (t == 0) g_rowptr[Nn] = sums[1023];
}

__global__ void k_scatter(const int* __restrict__ src, const int* __restrict__ dst) {
    int e = blockIdx.x * blockDim.x + threadIdx.x;
    if (e < Ee) {
        int d = dst[e];
        int p = atomicAdd(&g_cursor[d], 1);
        g_colsrc[p] = src[e];
    }
}

// canonicalize segment order (determinism regardless of atomic scatter order)
__global__ void __launch_bounds__(256) k_sortseg() {
    int w = (blockIdx.x * blockDim.x + threadIdx.x) >> 5;
    if (w >= Nn) return;
    int lane = threadIdx.x & 31;
    int s0 = g_rowptr[w], s1 = g_rowptr[w + 1];
    int deg = s1 - s0;
    if (deg <= 1) return;
    if (deg <= 32) {
        int v = (lane < deg) ? g_colsrc[s0 + lane] : 0x7fffffff;
#pragma unroll
        for (int k = 2; k <= 32; k <<= 1) {
#pragma unroll
            for (int j = k >> 1; j > 0; j >>= 1) {
                int pv = __shfl_xor_sync(FULL, v, j);
                int mn = min(v, pv), mx = max(v, pv);
                bool dir = ((lane & k) == 0);
                v = (((lane & j) == 0) == dir) ? mn : mx;
            }
        }
        if (lane < deg) g_colsrc[s0 + lane] = v;
    } else {
        if (lane == 0) {  // rare: insertion sort in place
            for (int i = s0 + 1; i < s1; i++) {
                int key = g_colsrc[i];
                int j = i - 1;
                while (j >= s0 && g_colsrc[j] > key) { g_colsrc[j + 1] = g_colsrc[j]; j--; }
                g_colsrc[j + 1] = key;
            }
        }
    }
}

// ---------------- SGEMM: C[N,128] = A[N,128] @ B[128,128] ----------------
__global__ void __launch_bounds__(256) k_gemm128(const float* __restrict__ A,
                                                 const float* __restrict__ B,
                                                 float* __restrict__ C, int nrows) {
    __shared__ float As[16][132];
    __shared__ float Bs[16][128];
    int tid = threadIdx.x;
    int brow = blockIdx.x * 128;
    int tx = tid & 15, ty = tid >> 4;
    float acc[8][8];
#pragma unroll
    for (int i = 0; i < 8; i++)
#pragma unroll
        for (int j = 0; j < 8; j++) acc[i][j] = 0.f;

    for (int k0 = 0; k0 < 128; k0 += 16) {
#pragma unroll
        for (int i = 0; i < 2; i++) {
            int m = (tid >> 2) + i * 64;
            int kk = (tid & 3) * 4;
            int gr = brow + m;
            float4 v = (gr < nrows) ? *(const float4*)(A + gr * 128 + k0 + kk)
                                    : make_float4(0.f, 0.f, 0.f, 0.f);
            As[kk + 0][m] = v.x; As[kk + 1][m] = v.y;
            As[kk + 2][m] = v.z; As[kk + 3][m] = v.w;
        }
#pragma unroll
        for (int i = 0; i < 2; i++) {
            int kk = (tid >> 5) + i * 8;
            int c = (tid & 31) * 4;
            *(float4*)(&Bs[kk][c]) = *(const float4*)(B + (k0 + kk) * 128 + c);
        }
        __syncthreads();
#pragma unroll
        for (int kk = 0; kk < 16; kk++) {
            float a[8], b[8];
            *(float4*)(a)     = *(const float4*)(&As[kk][ty * 8]);
            *(float4*)(a + 4) = *(const float4*)(&As[kk][ty * 8 + 4]);
            *(float4*)(b)     = *(const float4*)(&Bs[kk][tx * 8]);
            *(float4*)(b + 4) = *(const float4*)(&Bs[kk][tx * 8 + 4]);
#pragma unroll
            for (int i = 0; i < 8; i++)
#pragma unroll
                for (int j = 0; j < 8; j++) acc[i][j] = fmaf(a[i], b[j], acc[i][j]);
        }
        __syncthreads();
    }
#pragma unroll
    for (int i = 0; i < 8; i++) {
        int gr = brow + ty * 8 + i;
        if (gr < nrows) {
            float4 v0 = make_float4(acc[i][0], acc[i][1], acc[i][2], acc[i][3]);
            float4 v1 = make_float4(acc[i][4], acc[i][5], acc[i][6], acc[i][7]);
            *(float4*)(C + gr * 128 + tx * 8)     = v0;
            *(float4*)(C + gr * 128 + tx * 8 + 4) = v1;
        }
    }
}

// ---------------- fused layer-2 GEMM: h1 @ [W2 | R2W]  (N x 128 x 80) ----------------
__global__ void __launch_bounds__(256) k_gemm_w2(const float* __restrict__ A,
                                                 const float* __restrict__ W2,
                                                 const float* __restrict__ R2W,
                                                 const float* __restrict__ R2b,
                                                 int nrows) {
    __shared__ float As[16][132];
    __shared__ float Bs[16][80];
    int tid = threadIdx.x;
    int brow = blockIdx.x * 128;
    int tx = tid & 15, ty = tid >> 4;   // cols tx*5.., rows ty*8..
    float acc[8][5];
#pragma unroll
    for (int i = 0; i < 8; i++)
#pragma unroll
        for (int j = 0; j < 5; j++) acc[i][j] = 0.f;

    for (int k0 = 0; k0 < 128; k0 += 16) {
#pragma unroll
        for (int i = 0; i < 2; i++) {
            int m = (tid >> 2) + i * 64;
            int kk = (tid & 3) * 4;
            int gr = brow + m;
            float4 v = (gr < nrows) ? *(const float4*)(A + gr * 128 + k0 + kk)
                                    : make_float4(0.f, 0.f, 0.f, 0.f);
            As[kk + 0][m] = v.x; As[kk + 1][m] = v.y;
            As[kk + 2][m] = v.z; As[kk + 3][m] = v.w;
        }
#pragma unroll
        for (int i = 0; i < 5; i++) {
            int f = tid + i * 256;
            int kk = f / 80, c = f % 80;
            float v = (c < 40) ? W2[(k0 + kk) * 40 + c] : R2W[(k0 + kk) * 40 + c - 40];
            Bs[kk][c] = v;
        }
        __syncthreads();
#pragma unroll
        for (int kk = 0; kk < 16; kk++) {
            float a[8], b[5];
            *(float4*)(a)     = *(const float4*)(&As[kk][ty * 8]);
            *(float4*)(a + 4) = *(const float4*)(&As[kk][ty * 8 + 4]);
#pragma unroll
            for (int j = 0; j < 5; j++) b[j] = Bs[kk][tx * 5 + j];
#pragma unroll
            for (int i = 0; i < 8; i++)
#pragma unroll
                for (int j = 0; j < 5; j++) acc[i][j] = fmaf(a[i], b[j], acc[i][j]);
        }
        __syncthreads();
    }
#pragma unroll
    for (int i = 0; i < 8; i++) {
        int gr = brow + ty * 8 + i;
        if (gr < nrows) {
#pragma unroll
            for (int j = 0; j < 5; j++) {
                int c = tx * 5 + j;
                if (c < 40) g_h2p[gr * 40 + c] = acc[i][j];
                else        g_resid2[gr * 40 + c - 40] = acc[i][j] + R2b[c - 40];
            }
        }
    }
}

// ---------------- attention logits a_s, a_d per node (H=4, C=32) ----------------
__global__ void __launch_bounds__(256) k_attn(const float* __restrict__ h,
                                              const float* __restrict__ asp,
                                              const float* __restrict__ adp) {
    int w = (blockIdx.x * blockDim.x + threadIdx.x) >> 5;
    if (w >= Nn) return;
    int lane = threadIdx.x & 31;
    float4 hv = *(const float4*)(h + (size_t)w * 128 + lane * 4);
    float4 sv = *(const float4*)(asp + lane * 4);
    float4 dv = *(const float4*)(adp + lane * 4);
    float ds = hv.x * sv.x + hv.y * sv.y + hv.z * sv.z + hv.w * sv.w;
    float dd = hv.x * dv.x + hv.y * dv.y + hv.z * dv.z + hv.w * dv.w;
#pragma unroll
    for (int o = 4; o; o >>= 1) {
        ds += __shfl_xor_sync(FULL, ds, o);
        dd += __shfl_xor_sync(FULL, dd, o);
    }
    if ((lane & 7) == 0) {
        g_as[w * 4 + (lane >> 3)] = ds;
        g_ad[w * 4 + (lane >> 3)] = dd;
    }
}

// ---------------- attention logits for layer 2 (H=1, C=40) ----------------
__global__ void __launch_bounds__(256) k_attn2(const float* __restrict__ asp,
                                               const float* __restrict__ adp) {
    int w = (blockIdx.x * blockDim.x + threadIdx.x) >> 5;
    if (w >= Nn) return;
    int lane = threadIdx.x & 31;
    float hv = g_h2p[w * 40 + lane];
    float ds = hv * asp[lane];
    float dd = hv * adp[lane];
    if (lane < 8) {
        float h2 = g_h2p[w * 40 + 32 + lane];
        ds += h2 * asp[32 + lane];
        dd += h2 * adp[32 + lane];
    }
    ds = wred_sum(ds);
    dd = wred_sum(dd);
    if (lane == 0) { g_as2[w] = ds; g_ad2[w] = dd; }
}

// ---------------- GAT aggregation, 128-wide, H=4 (warp per dst, online softmax) --------
template <bool HAS_RES>
__global__ void __launch_bounds__(256) k_agg128(const float* __restrict__ h,
                                                const float* __restrict__ bias,
                                                const float* __restrict__ resid,
                                                const float* __restrict__ rbias,
                                                float* __restrict__ out) {
    int w = (blockIdx.x * blockDim.x + threadIdx.x) >> 5;
    if (w >= Nn) return;
    int lane = threadIdx.x & 31;
    int s0 = g_rowptr[w], s1 = g_rowptr[w + 1];
    float4 adv = *(const float4*)(g_ad + w * 4);
    float m0 = -1e30f, m1 = -1e30f, m2 = -1e30f, m3 = -1e30f;
    float ss0 = 0.f, ss1 = 0.f, ss2 = 0.f, ss3 = 0.f;
    float4 acc = make_float4(0.f, 0.f, 0.f, 0.f);
    int myhead = lane >> 3;

    for (int base = s0; base < s1; base += 32) {
        int idx = base + lane;
        bool valid = idx < s1;
        int src = valid ? g_colsrc[idx] : 0;
        float4 av = *(const float4*)(g_as + src * 4);
        float a0 = valid ? lrelu(av.x + adv.x) : -1e30f;
        float a1 = valid ? lrelu(av.y + adv.y) : -1e30f;
        float a2 = valid ? lrelu(av.z + adv.z) : -1e30f;
        float a3 = valid ? lrelu(av.w + adv.w) : -1e30f;
        float n0 = fmaxf(m0, wred_max(a0));
        float n1 = fmaxf(m1, wred_max(a1));
        float n2 = fmaxf(m2, wred_max(a2));
        float n3 = fmaxf(m3, wred_max(a3));
        float f0 = __expf(m0 - n0), f1 = __expf(m1 - n1);
        float f2 = __expf(m2 - n2), f3 = __expf(m3 - n3);
        float e0 = __expf(a0 - n0), e1 = __expf(a1 - n1);
        float e2 = __expf(a2 - n2), e3 = __expf(a3 - n3);
        ss0 = ss0 * f0 + wred_sum(e0);
        ss1 = ss1 * f1 + wred_sum(e1);
        ss2 = ss2 * f2 + wred_sum(e2);
        ss3 = ss3 * f3 + wred_sum(e3);
        m0 = n0; m1 = n1; m2 = n2; m3 = n3;
        float af = myhead == 0 ? f0 : myhead == 1 ? f1 : myhead == 2 ? f2 : f3;
        acc.x *= af; acc.y *= af; acc.z *= af; acc.w *= af;
        int cnt = min(32, s1 - base);
        for (int j = 0; j < cnt; j++) {
            int sj = __shfl_sync(FULL, src, j);
            float w0 = __shfl_sync(FULL, e0, j);
            float w1 = __shfl_sync(FULL, e1, j);
            float w2 = __shfl_sync(FULL, e2, j);
            float w3 = __shfl_sync(FULL, e3, j);
            float wt = myhead == 0 ? w0 : myhead == 1 ? w1 : myhead == 2 ? w2 : w3;
            float4 v = *(const float4*)(h + (size_t)sj * 128 + lane * 4);
            acc.x = fmaf(wt, v.x, acc.x);
            acc.y = fmaf(wt, v.y, acc.y);
            acc.z = fmaf(wt, v.z, acc.z);
            acc.w = fmaf(wt, v.w, acc.w);
        }
    }
    float sden = myhead == 0 ? ss0 : myhead == 1 ? ss1 : myhead == 2 ? ss2 : ss3;
    float inv = 1.0f / (sden + 1e-16f);
    int cb = lane * 4;
    float4 b = *(const float4*)(bias + cb);
    float4 o;
    o.x = fmaxf(acc.x * inv + b.x, 0.f);
    o.y = fmaxf(acc.y * inv + b.y, 0.f);
    o.z = fmaxf(acc.z * inv + b.z, 0.f);
    o.w = fmaxf(acc.w * inv + b.w, 0.f);
    if (HAS_RES) {
        float4 r = *(const float4*)(resid + (size_t)w * 128 + cb);
        float4 rb = *(const float4*)(rbias + cb);
        o.x += r.x + rb.x; o.y += r.y + rb.y;
        o.z += r.z + rb.z; o.w += r.w + rb.w;
    }
    *(float4*)(out + (size_t)w * 128 + cb) = o;
}

// ---------------- GAT aggregation, 40-wide, H=1 ----------------
__global__ void __launch_bounds__(256) k_agg40(const float* __restrict__ bias) {
    int w = (blockIdx.x * blockDim.x + threadIdx.x) >> 5;
    if (w >= Nn) return;
    int lane = threadIdx.x & 31;
    int s0 = g_rowptr[w], s1 = g_rowptr[w + 1];
    float adv = g_ad2[w];
    float m = -1e30f, ss = 0.f;
    float2 acc = make_float2(0.f, 0.f);
    for (int base = s0; base < s1; base += 32) {
        int idx = base + lane;
        bool valid = idx < s1;
        int src = valid ? g_colsrc[idx] : 0;
        float a = valid ? lrelu(g_as2[src] + adv) : -1e30f;
        float n = fmaxf(m, wred_max(a));
        float f = __expf(m - n);
        float e = __expf(a - n);
        ss = ss * f + wred_sum(e);
        m = n;
        acc.x *= f; acc.y *= f;
        int cnt = min(32, s1 - base);
        for (int j = 0; j < cnt; j++) {
            int sj = __shfl_sync(FULL, src, j);
            float wt = __shfl_sync(FULL, e, j);
            if (lane < 20) {
                float2 v = *(const float2*)(g_h2p + sj * 40 + lane * 2);
                acc.x = fmaf(wt, v.x, acc.x);
                acc.y = fmaf(wt, v.y, acc.y);
            }
        }
    }
    if (lane < 20) {
        float inv = 1.0f / (ss + 1e-16f);
        float2 b = *(const float2*)(bias + lane * 2);
        float2 r = *(const float2*)(g_resid2 + w * 40 + lane * 2);
        float2 o;
        o.x = fmaxf(acc.x * inv + b.x, 0.f) + r.x;
        o.y = fmaxf(acc.y * inv + b.y, 0.f) + r.y;
        *(float2*)(g_h2 + w * 40 + lane * 2) = o;
    }
}

// ---------------- final: logits = h2 @ LW + Lb, log_softmax ----------------
__global__ void __launch_bounds__(256) k_final(const float* __restrict__ LW,
                                               const float* __restrict__ Lb,
                                               float* __restrict__ out) {
    __shared__ float sW[1600];
    __shared__ float sb[40];
    int tid = threadIdx.x;
    for (int i = tid; i < 1600; i += 256) sW[i] = LW[i];
    if (tid < 40) sb[tid] = Lb[tid];
    __syncthreads();
    int w = (blockIdx.x * 256 + tid) >> 5;
    if (w >= Nn) return;
    int lane = tid & 31;
    float x0 = g_h2[w * 40 + lane];
    float x1 = (lane < 8) ? g_h2[w * 40 + 32 + lane] : 0.f;
    float acc0 = sb[lane];
    float acc1 = (lane < 8) ? sb[32 + lane] : 0.f;
#pragma unroll
    for (int k = 0; k < 40; k++) {
        float xk = (k < 32) ? __shfl_sync(FULL, x0, k) : __shfl_sync(FULL, x1, k - 32);
        acc0 = fmaf(xk, sW[k * 40 + lane], acc0);
        if (lane < 8) acc1 = fmaf(xk, sW[k * 40 + 32 + lane], acc1);
    }
    float mx = (lane < 8) ? fmaxf(acc0, acc1) : acc0;
    mx = wred_max(mx);
    float es = __expf(acc0 - mx) + ((lane < 8) ? __expf(acc1 - mx) : 0.f);
    es = wred_sum(es);
    float lse = mx + logf(es);
    out[w * 40 + lane] = acc0 - lse;
    if (lane < 8) out[w * 40 + 32 + lane] = acc1 - lse;
}

// ---------------- launch ----------------
extern "C" void kernel_launch(void* const* d_in, const int* in_sizes, int n_in,
                              void* d_out, int out_size) {
    const float* x   = (const float*)d_in[0];
    const int*   ei  = (const int*)d_in[1];
    const float* W0  = (const float*)d_in[2];
    const float* as0 = (const float*)d_in[3];
    const float* ad0 = (const float*)d_in[4];
    const float* b0  = (const float*)d_in[5];
    const float* W1  = (const float*)d_in[6];
    const float* as1 = (const float*)d_in[7];
    const float* ad1 = (const float*)d_in[8];
    const float* b1  = (const float*)d_in[9];
    const float* R1W = (const float*)d_in[10];
    const float* R1b = (const float*)d_in[11];
    const float* W2  = (const float*)d_in[12];
    const float* as2 = (const float*)d_in[13];
    const float* ad2 = (const float*)d_in[14];
    const float* b2  = (const float*)d_in[15];
    const float* R2W = (const float*)d_in[16];
    const float* R2b = (const float*)d_in[17];
    const float* LW  = (const float*)d_in[18];
    const float* Lb  = (const float*)d_in[19];
    float* out = (float*)d_out;
    const int* esrc = ei;
    const int* edst = ei + Ee;

    float *p_h, *p_out0, *p_out1, *p_resid;
    cudaGetSymbolAddress((void**)&p_h, g_h);
    cudaGetSymbolAddress((void**)&p_out0, g_out0);
    cudaGetSymbolAddress((void**)&p_out1, g_out1);
    cudaGetSymbolAddress((void**)&p_resid, g_resid);

    const int WB = 6250;  // 50000 warps / 8 warps per 256-thread block

    // CSR build (deterministic: canonical sort per segment)
    k_init<<<(Nn + 255) / 256, 256>>>();
    k_hist<<<(Ee + 255) / 256, 256>>>(edst);
    k_scan<<<1, 1024>>>();
    k_scatter<<<(Ee + 255) / 256, 256>>>(esrc, edst);
    k_sortseg<<<WB, 256>>>();

    const int GB = (Nn + 127) / 128;  // 391 GEMM blocks

    // layer 0
    k_gemm128<<<GB, 256>>>(x, W0, p_h, Nn);
    k_attn<<<WB, 256>>>(p_h, as0, ad0);
    k_agg128<false><<<WB, 256>>>(p_h, b0, nullptr, nullptr, p_out0);

    // layer 1
    k_gemm128<<<GB, 256>>>(p_out0, W1, p_h, Nn);
    k_gemm128<<<GB, 256>>>(p_out0, R1W, p_resid, Nn);
    k_attn<<<WB, 256>>>(p_h, as1, ad1);
    k_agg128<true><<<WB, 256>>>(p_h, b1, p_resid, R1b, p_out1);

    // layer 2
    k_gemm_w2<<<GB, 256>>>(p_out1, W2, R2W, R2b, Nn);
    k_attn2<<<WB, 256>>>(as2, ad2);
    k_agg40<<<WB, 256>>>(b2);

    // final linear + log_softmax
    k_final<<<WB, 256>>>(LW, Lb, out);
}